// round 8
// baseline (speedup 1.0000x reference)
#include <cuda_runtime.h>
#include <cstdint>

// SSIM over 11x11 patches — persistent-ish double-buffered cp.async pipeline.
// img_pred: [4, 2048, 16, 121, 3] f32   (~190 MB)
// img_gt:   [2048, 16, 121, 3] f32      (~47.6 MB)
// out:      [4, 2048, 16] f32
//
// R7 showed DRAM idle ~31% (bytes already minimal): blocks alternate
// stage/compute with nothing in flight during compute. R8: each block
// owns 8 chunks (chunk = 2 consecutive (n,p) rows) and double-buffers:
// stage chunk i+1 (cp.async.ca 8B — 2-row chunks are 8B- not 16B-aligned)
// while computing chunk i. 64-thread blocks (warp = row, 4 views, R7's
// inner loop). 2 bufs x 5 streams x 768 floats ~= 30.7KB -> 7 blocks/SM,
// every block always has a chunk of loads outstanding.

#define NN       2048
#define NP       16
#define ROW      363                       // 121 patches * 3 channels
#define VSTRIDE  ((size_t)NN * NP * ROW)   // floats per view
#define RPC      2                         // rows per chunk
#define CH       (RPC * ROW)               // 726 floats per stream per chunk
#define CH2      (CH / 2)                  // 363 float2
#define CHPAD    768                       // padded buffer row (zero tail)
#define KCH      8                         // chunks per block
#define NTHR     64

__device__ __forceinline__ void cp8(uint32_t dst, const void* src) {
    asm volatile("cp.async.ca.shared.global [%0], [%1], 8;" :: "r"(dst), "l"(src));
}

__global__ __launch_bounds__(NTHR) void ssim_kernel(
    const float* __restrict__ pred,
    const float* __restrict__ gt,
    float* __restrict__ out)
{
    __shared__ float sG[2][CHPAD];        // gt
    __shared__ float sP[4][2][CHPAD];     // pred views (view-major for addr math)
    __shared__ float sg6[6];
    __shared__ float sW[128];             // per-patch weights, 0 for p>=121

    const int tid  = threadIdx.x;
    const int wid  = tid >> 5;
    const int lane = tid & 31;

    // ---- one-time block setup: zero pads, build weight table ----
    for (int i = tid; i < CHPAD - CH; i += NTHR) {
        sG[0][CH + i] = 0.f;  sG[1][CH + i] = 0.f;
        #pragma unroll
        for (int v = 0; v < 4; v++) { sP[v][0][CH + i] = 0.f; sP[v][1][CH + i] = 0.f; }
    }
    if (tid < 6) {
        float d = (float)tid;
        sg6[tid] = expf(-d * d * (1.0f / 4.5f));   // sigma = 1.5
    }
    __syncthreads();
    {
        float S = sg6[0] + 2.0f * (sg6[1] + sg6[2] + sg6[3] + sg6[4] + sg6[5]);
        float invS2 = 1.0f / (S * S);
        for (int t = tid; t < 128; t += NTHR) {
            if (t < 121) {
                int py = t / 11, px = t % 11;
                int dy = py - 5; if (dy < 0) dy = -dy;
                int dx = px - 5; if (dx < 0) dx = -dx;
                sW[t] = sg6[dy] * sg6[dx] * invS2;
            } else {
                sW[t] = 0.f;
            }
        }
    }
    __syncthreads();

    float wk[4];
    #pragma unroll
    for (int k = 0; k < 4; k++) wk[k] = sW[k * 32 + lane];

    const int c0 = blockIdx.x * KCH;      // first chunk of this block

    // ---- stage helper (macro to keep cp.async src/dst computation tight) ----
    #define STAGE(buf, cidx) do {                                              \
        const size_t goff = (size_t)(cidx) * CH;                               \
        const float2* __restrict__ srcG = (const float2*)(gt + goff);          \
        uint32_t dG = (uint32_t)__cvta_generic_to_shared(&sG[(buf)][0]);       \
        for (int i = tid; i < CH2; i += NTHR)                                  \
            cp8(dG + i * 8, srcG + i);                                         \
        _Pragma("unroll")                                                      \
        for (int v = 0; v < 4; v++) {                                          \
            const float2* __restrict__ srcP =                                  \
                (const float2*)(pred + v * VSTRIDE + goff);                    \
            uint32_t dP = (uint32_t)__cvta_generic_to_shared(&sP[v][(buf)][0]);\
            for (int i = tid; i < CH2; i += NTHR)                              \
                cp8(dP + i * 8, srcP + i);                                     \
        }                                                                      \
        asm volatile("cp.async.commit_group;");                                \
    } while (0)

    STAGE(0, c0);

    #pragma unroll 1
    for (int i = 0; i < KCH; i++) {
        const int buf = i & 1;
        if (i + 1 < KCH) {
            STAGE(buf ^ 1, c0 + i + 1);
            asm volatile("cp.async.wait_group 1;");
        } else {
            asm volatile("cp.async.wait_group 0;");
        }
        __syncthreads();   // staged data (written by both warps) visible to all

        // ---- compute: warp w = row w of this chunk, all 4 views ----
        const int wbase = wid * ROW;
        const float* __restrict__ bG = &sG[0][0] + buf * CHPAD + wbase;

        float m1[4][3], q2[4][3], pg[4][3];
        float m2[3], g2[3];
        #pragma unroll
        for (int v = 0; v < 4; v++)
            #pragma unroll
            for (int c = 0; c < 3; c++) { m1[v][c] = 0.f; q2[v][c] = 0.f; pg[v][c] = 0.f; }
        #pragma unroll
        for (int c = 0; c < 3; c++) { m2[c] = 0.f; g2[c] = 0.f; }

        #pragma unroll
        for (int k = 0; k < 4; k++) {
            const int base = 3 * (k * 32 + lane);
            const float w = wk[k];              // 0 for pad patches
            const float b0 = bG[base + 0];
            const float b1 = bG[base + 1];
            const float b2 = bG[base + 2];
            const float wb0 = w * b0, wb1 = w * b1, wb2 = w * b2;
            m2[0] += wb0;       m2[1] += wb1;       m2[2] += wb2;
            g2[0] += wb0 * b0;  g2[1] += wb1 * b1;  g2[2] += wb2 * b2;

            #pragma unroll
            for (int v = 0; v < 4; v++) {
                const float* __restrict__ bP = &sP[v][0][0] + buf * CHPAD + wbase;
                const float a0 = bP[base + 0];
                const float a1 = bP[base + 1];
                const float a2 = bP[base + 2];
                const float wa0 = w * a0, wa1 = w * a1, wa2 = w * a2;
                m1[v][0] += wa0;       m1[v][1] += wa1;       m1[v][2] += wa2;
                q2[v][0] += wa0 * a0;  q2[v][1] += wa1 * a1;  q2[v][2] += wa2 * a2;
                pg[v][0] += wa0 * b0;  pg[v][1] += wa1 * b1;  pg[v][2] += wa2 * b2;
            }
        }

        // Fold across lane-bit-16: lanes 0-15 -> views 0,1; 16-31 -> views 2,3.
        const bool hi = (lane & 16) != 0;
        float val[24];
        #pragma unroll
        for (int c = 0; c < 3; c++) {
            float kA, kB;
            #define FOLD(slotA, slotB, idx) \
                kA = (slotA); kB = (slotB); \
                { float keep = hi ? kB : kA; float send = hi ? kA : kB; \
                  val[idx] = keep + __shfl_xor_sync(0xFFFFFFFFu, send, 16); }
            FOLD(m1[0][c], m1[2][c], 0 + c);
            FOLD(q2[0][c], q2[2][c], 3 + c);
            FOLD(pg[0][c], pg[2][c], 6 + c);
            FOLD(m1[1][c], m1[3][c], 9 + c);
            FOLD(q2[1][c], q2[3][c], 12 + c);
            FOLD(pg[1][c], pg[3][c], 15 + c);
            FOLD(m2[c],    m2[c],    18 + c);
            FOLD(g2[c],    g2[c],    21 + c);
            #undef FOLD
        }

        #pragma unroll
        for (int off = 8; off; off >>= 1) {
            #pragma unroll
            for (int t = 0; t < 24; t++)
                val[t] += __shfl_xor_sync(0xFFFFFFFFu, val[t], off);
        }

        const float C1 = 1e-4f;   // 0.01^2
        const float C2 = 9e-4f;   // 0.03^2
        float ssim_lo = 0.f, ssim_hi_v = 0.f;
        #pragma unroll
        for (int c = 0; c < 3; c++) {
            float mu2  = val[18 + c];
            float mu2sq = mu2 * mu2;
            float s2   = val[21 + c] - mu2sq;
            {
                float mu1 = val[0 + c];
                float mu1sq = mu1 * mu1;
                float mu12  = mu1 * mu2;
                float s1  = val[3 + c] - mu1sq;
                float s12 = val[6 + c] - mu12;
                float num = (2.0f * mu12 + C1) * (2.0f * s12 + C2);
                float den = (mu1sq + mu2sq + C1) * (s1 + s2 + C2);
                ssim_lo += __fdividef(num, den);
            }
            {
                float mu1 = val[9 + c];
                float mu1sq = mu1 * mu1;
                float mu12  = mu1 * mu2;
                float s1  = val[12 + c] - mu1sq;
                float s12 = val[15 + c] - mu12;
                float num = (2.0f * mu12 + C1) * (2.0f * s12 + C2);
                float den = (mu1sq + mu2sq + C1) * (s1 + s2 + C2);
                ssim_hi_v += __fdividef(num, den);
            }
        }

        if ((lane & 14) == 0) {
            const int q = (c0 + i) * RPC + wid;    // global (n,p) row
            const int n = q >> 4;
            const int p = q & 15;
            int sel  = lane & 1;
            int view = ((lane >> 4) << 1) | sel;
            float res = (sel ? ssim_hi_v : ssim_lo) * (1.0f / 3.0f);
            out[(view * NN + n) * NP + p] = res;
        }

        __syncthreads();   // buffer 'buf' free before iter i+1 stages into it
    }
    #undef STAGE
}

extern "C" void kernel_launch(void* const* d_in, const int* in_sizes, int n_in,
                              void* d_out, int out_size)
{
    const float* pred = (const float*)d_in[0];   // img_pred [4,2048,16,121,3]
    const float* gt   = (const float*)d_in[1];   // img_gt   [2048,16,121,3]
    float* out = (float*)d_out;                  // [4,2048,16]

    // 32768 (n,p) rows -> 16384 chunks of 2 rows -> 2048 blocks of 8 chunks.
    const int blocks = (NN * NP) / (RPC * KCH);  // 2048
    ssim_kernel<<<blocks, NTHR>>>(pred, gt, out);
}

// round 9
// speedup vs baseline: 1.4529x; 1.4529x over previous
#include <cuda_runtime.h>
#include <cstdint>

// SSIM over 11x11 patches — cp.async staging with per-stream wait groups.
// img_pred: [4, 2048, 16, 121, 3] f32   (~190 MB)
// img_gt:   [2048, 16, 121, 3] f32      (~47.6 MB)
// out:      [4, 2048, 16] f32
//
// R7 base (128-thr block = 4 rows, 16B cp.async, patch-major smem compute)
// + staged waits: each of the 5 streams (gt, view0..3) is its own commit
// group; compute gt stats after wait_group 4, view v after wait_group 3-v.
// Compute overlaps the still-arriving later streams instead of idling at a
// single wait_group 0. b re-read from smem per view (48 extra LDS) to keep
// regs <= ~71 so 7 blocks/SM survive (RF co-limit discovered in R7/R8).

#define NN       2048
#define NP       16
#define ROW      363                       // 121 patches * 3 channels
#define VSTRIDE  ((size_t)NN * NP * ROW)   // floats per view
#define RPB      4                         // rows per block
#define CHUNK    (RPB * ROW)               // 1452 floats
#define CHUNK4   (CHUNK / 4)               // 363 float4
#define PADF     32                        // zeroed pad floats per array

__device__ __forceinline__ void cp16(uint32_t dst, const void* src) {
    asm volatile("cp.async.cg.shared.global [%0], [%1], 16;" :: "r"(dst), "l"(src));
}

__global__ __launch_bounds__(128) void ssim_kernel(
    const float* __restrict__ pred,
    const float* __restrict__ gt,
    float* __restrict__ out)
{
    __shared__ float sG[CHUNK + PADF];       // gt, 4 rows (+pad)
    __shared__ float sP[4][CHUNK + PADF];    // pred, 4 views x 4 rows (+pad)
    __shared__ float sg6[6];                 // 1-D gaussian, |d| = 0..5
    __shared__ float sW[128];                // per-patch weights, 0 for p>=121

    const int tid = threadIdx.x;
    const int q0  = blockIdx.x * RPB;        // first (n,p) row of this block

    // ---- stage: 5 streams, each its own commit group (issue order matters) ----
    {
        const uint32_t dG = (uint32_t)__cvta_generic_to_shared(sG);
        const float4* __restrict__ srcG = (const float4*)(gt + (size_t)q0 * ROW);
        for (int i = tid; i < CHUNK4; i += 128)
            cp16(dG + i * 16, srcG + i);
        asm volatile("cp.async.commit_group;");          // group: gt

        #pragma unroll
        for (int v = 0; v < 4; v++) {
            const uint32_t dP = (uint32_t)__cvta_generic_to_shared(sP[v]);
            const float4* __restrict__ srcP =
                (const float4*)(pred + v * VSTRIDE + (size_t)q0 * ROW);
            for (int i = tid; i < CHUNK4; i += 128)
                cp16(dP + i * 16, srcP + i);
            asm volatile("cp.async.commit_group;");      // group: view v
        }
    }

    // ---- while loads fly: zero pads, build weight table ----
    if (tid < PADF) {
        sG[CHUNK + tid] = 0.f;
        sP[0][CHUNK + tid] = 0.f;
        sP[1][CHUNK + tid] = 0.f;
        sP[2][CHUNK + tid] = 0.f;
        sP[3][CHUNK + tid] = 0.f;
    }
    if (tid < 6) {
        float d = (float)tid;
        sg6[tid] = expf(-d * d * (1.0f / 4.5f));   // sigma = 1.5
    }
    __syncthreads();
    {
        float S = sg6[0] + 2.0f * (sg6[1] + sg6[2] + sg6[3] + sg6[4] + sg6[5]);
        float invS2 = 1.0f / (S * S);
        if (tid < 121) {
            int py = tid / 11, px = tid % 11;
            int dy = py - 5; if (dy < 0) dy = -dy;
            int dx = px - 5; if (dx < 0) dx = -dx;
            sW[tid] = sg6[dy] * sg6[dx] * invS2;
        } else if (tid < 128) {
            sW[tid] = 0.f;                          // tail patches contribute 0
        }
    }

    const int wid  = tid >> 5;
    const int lane = tid & 31;
    const int wbase = wid * ROW;

    float wk[4];
    #pragma unroll
    for (int k = 0; k < 4; k++) wk[k] = sW[k * 32 + lane];   // after sW build? no!
    // NOTE: sW build above is by tid<128 threads; need a barrier before use.
    // The wait below includes __syncthreads which also publishes sW.

    float m1[4][3], q2[4][3], pg[4][3];
    float m2[3], g2[3];
    #pragma unroll
    for (int v = 0; v < 4; v++)
        #pragma unroll
        for (int c = 0; c < 3; c++) { m1[v][c] = 0.f; q2[v][c] = 0.f; pg[v][c] = 0.f; }
    #pragma unroll
    for (int c = 0; c < 3; c++) { m2[c] = 0.f; g2[c] = 0.f; }

    // ---- gt stats as soon as the gt group lands (views still in flight) ----
    asm volatile("cp.async.wait_group 4;");
    __syncthreads();          // publishes gt buffer, pads, and sW to all warps
    #pragma unroll
    for (int k = 0; k < 4; k++) wk[k] = sW[k * 32 + lane];   // real load (post-barrier)
    #pragma unroll
    for (int k = 0; k < 4; k++) {
        const int base = wbase + 3 * (k * 32 + lane);
        const float w = wk[k];
        const float b0 = sG[base + 0];
        const float b1 = sG[base + 1];
        const float b2 = sG[base + 2];
        m2[0] += w * b0;        m2[1] += w * b1;        m2[2] += w * b2;
        g2[0] += w * b0 * b0;   g2[1] += w * b1 * b1;   g2[2] += w * b2 * b2;
    }

    // ---- per-view stats as each view group lands ----
    #pragma unroll
    for (int v = 0; v < 4; v++) {
        if (v == 0) asm volatile("cp.async.wait_group 3;");
        if (v == 1) asm volatile("cp.async.wait_group 2;");
        if (v == 2) asm volatile("cp.async.wait_group 1;");
        if (v == 3) asm volatile("cp.async.wait_group 0;");
        __syncthreads();      // view v buffer visible block-wide

        #pragma unroll
        for (int k = 0; k < 4; k++) {
            const int base = wbase + 3 * (k * 32 + lane);
            const float w = wk[k];
            const float b0 = sG[base + 0];
            const float b1 = sG[base + 1];
            const float b2 = sG[base + 2];
            const float a0 = sP[v][base + 0];
            const float a1 = sP[v][base + 1];
            const float a2 = sP[v][base + 2];
            const float wa0 = w * a0, wa1 = w * a1, wa2 = w * a2;
            m1[v][0] += wa0;       m1[v][1] += wa1;       m1[v][2] += wa2;
            q2[v][0] += wa0 * a0;  q2[v][1] += wa1 * a1;  q2[v][2] += wa2 * a2;
            pg[v][0] += wa0 * b0;  pg[v][1] += wa1 * b1;  pg[v][2] += wa2 * b2;
        }
    }

    // Fold across lane-bit-16: lanes 0-15 -> views 0,1; 16-31 -> views 2,3.
    const bool hi = (lane & 16) != 0;
    float val[24];
    #pragma unroll
    for (int c = 0; c < 3; c++) {
        float kA, kB;
        #define FOLD(slotA, slotB, idx) \
            kA = (slotA); kB = (slotB); \
            { float keep = hi ? kB : kA; float send = hi ? kA : kB; \
              val[idx] = keep + __shfl_xor_sync(0xFFFFFFFFu, send, 16); }
        FOLD(m1[0][c], m1[2][c], 0 + c);
        FOLD(q2[0][c], q2[2][c], 3 + c);
        FOLD(pg[0][c], pg[2][c], 6 + c);
        FOLD(m1[1][c], m1[3][c], 9 + c);
        FOLD(q2[1][c], q2[3][c], 12 + c);
        FOLD(pg[1][c], pg[3][c], 15 + c);
        FOLD(m2[c],    m2[c],    18 + c);   // single copy -> both halves get total
        FOLD(g2[c],    g2[c],    21 + c);
        #undef FOLD
    }

    // Butterfly within each 16-lane half.
    #pragma unroll
    for (int off = 8; off; off >>= 1) {
        #pragma unroll
        for (int i = 0; i < 24; i++)
            val[i] += __shfl_xor_sync(0xFFFFFFFFu, val[i], off);
    }

    // Epilogue: each lane computes SSIM for its half's two views.
    const float C1 = 1e-4f;   // 0.01^2
    const float C2 = 9e-4f;   // 0.03^2
    float ssim_lo = 0.f, ssim_hi_v = 0.f;
    #pragma unroll
    for (int c = 0; c < 3; c++) {
        float mu2  = val[18 + c];
        float mu2sq = mu2 * mu2;
        float s2   = val[21 + c] - mu2sq;
        {   // view lo
            float mu1 = val[0 + c];
            float mu1sq = mu1 * mu1;
            float mu12  = mu1 * mu2;
            float s1  = val[3 + c] - mu1sq;
            float s12 = val[6 + c] - mu12;
            float num = (2.0f * mu12 + C1) * (2.0f * s12 + C2);
            float den = (mu1sq + mu2sq + C1) * (s1 + s2 + C2);
            ssim_lo += __fdividef(num, den);
        }
        {   // view hi
            float mu1 = val[9 + c];
            float mu1sq = mu1 * mu1;
            float mu12  = mu1 * mu2;
            float s1  = val[12 + c] - mu1sq;
            float s12 = val[15 + c] - mu12;
            float num = (2.0f * mu12 + C1) * (2.0f * s12 + C2);
            float den = (mu1sq + mu2sq + C1) * (s1 + s2 + C2);
            ssim_hi_v += __fdividef(num, den);
        }
    }

    // Writers: lanes 0,1 (views 0,1) and 16,17 (views 2,3).
    if ((lane & 14) == 0) {
        const int q = q0 + wid;
        const int n = q >> 4;
        const int p = q & 15;
        int sel  = lane & 1;
        int view = ((lane >> 4) << 1) | sel;
        float res = (sel ? ssim_hi_v : ssim_lo) * (1.0f / 3.0f);
        out[(view * NN + n) * NP + p] = res;
    }
}

extern "C" void kernel_launch(void* const* d_in, const int* in_sizes, int n_in,
                              void* d_out, int out_size)
{
    const float* pred = (const float*)d_in[0];   // img_pred [4,2048,16,121,3]
    const float* gt   = (const float*)d_in[1];   // img_gt   [2048,16,121,3]
    float* out = (float*)d_out;                  // [4,2048,16]

    const int blocks = (NN * NP) / RPB;          // 8192 blocks, 4 rows each
    ssim_kernel<<<blocks, 128>>>(pred, gt, out);
}

// round 10
// speedup vs baseline: 1.5007x; 1.0329x over previous
#include <cuda_runtime.h>
#include <cstdint>

// SSIM over 11x11 patches — cp.async staging, register-cached gt, f32x2 math.
// img_pred: [4, 2048, 16, 121, 3] f32   (~190 MB)
// img_gt:   [2048, 16, 121, 3] f32      (~47.6 MB)
// out:      [4, 2048, 16] f32
//
// R9 -> R10: (1) gt row cached in registers across all 4 views (12 regs,
// loaded once in the gt phase) -> LDS/warp ~108 -> ~64 (near the read-once
// minimum); (2) channels 0,1 of every statistic computed with packed
// fma.rn.f32x2 / mul.rn.f32x2 / add.rn.f32x2 (per-lane rounding identical
// to scalar -> bit-identical results), cutting fma-pipe ops per view-k
// from 12 to 8. Staging: 5 commit groups; gt phase overlaps view arrivals,
// then k-outer/v-inner compute amortizes per-k packs over 4 views.

#define NN       2048
#define NP       16
#define ROW      363                       // 121 patches * 3 channels
#define VSTRIDE  ((size_t)NN * NP * ROW)   // floats per view
#define RPB      4                         // rows per block
#define CHUNK    (RPB * ROW)               // 1452 floats
#define CHUNK4   (CHUNK / 4)               // 363 float4
#define PADF     32                        // zeroed pad floats per array

using ull = unsigned long long;

__device__ __forceinline__ void cp16(uint32_t dst, const void* src) {
    asm volatile("cp.async.cg.shared.global [%0], [%1], 16;" :: "r"(dst), "l"(src));
}
__device__ __forceinline__ ull pk2(float lo, float hi) {
    ull r; asm("mov.b64 %0, {%1, %2};" : "=l"(r) : "f"(lo), "f"(hi)); return r;
}
__device__ __forceinline__ void up2(ull v, float& lo, float& hi) {
    asm("mov.b64 {%0, %1}, %2;" : "=f"(lo), "=f"(hi) : "l"(v));
}
__device__ __forceinline__ ull fma2_(ull a, ull b, ull c) {
    ull d; asm("fma.rn.f32x2 %0, %1, %2, %3;" : "=l"(d) : "l"(a), "l"(b), "l"(c)); return d;
}
__device__ __forceinline__ ull mul2_(ull a, ull b) {
    ull d; asm("mul.rn.f32x2 %0, %1, %2;" : "=l"(d) : "l"(a), "l"(b)); return d;
}
__device__ __forceinline__ ull add2_(ull a, ull b) {
    ull d; asm("add.rn.f32x2 %0, %1, %2;" : "=l"(d) : "l"(a), "l"(b)); return d;
}

__global__ __launch_bounds__(128) void ssim_kernel(
    const float* __restrict__ pred,
    const float* __restrict__ gt,
    float* __restrict__ out)
{
    __shared__ float sG[CHUNK + PADF];       // gt, 4 rows (+pad)
    __shared__ float sP[4][CHUNK + PADF];    // pred, 4 views x 4 rows (+pad)
    __shared__ float sg6[6];                 // 1-D gaussian, |d| = 0..5
    __shared__ float sW[128];                // per-patch weights, 0 for p>=121

    const int tid = threadIdx.x;
    const int q0  = blockIdx.x * RPB;        // first (n,p) row of this block

    // ---- stage: 5 streams, each its own commit group ----
    {
        const uint32_t dG = (uint32_t)__cvta_generic_to_shared(sG);
        const float4* __restrict__ srcG = (const float4*)(gt + (size_t)q0 * ROW);
        for (int i = tid; i < CHUNK4; i += 128)
            cp16(dG + i * 16, srcG + i);
        asm volatile("cp.async.commit_group;");          // group: gt

        #pragma unroll
        for (int v = 0; v < 4; v++) {
            const uint32_t dP = (uint32_t)__cvta_generic_to_shared(sP[v]);
            const float4* __restrict__ srcP =
                (const float4*)(pred + v * VSTRIDE + (size_t)q0 * ROW);
            for (int i = tid; i < CHUNK4; i += 128)
                cp16(dP + i * 16, srcP + i);
            asm volatile("cp.async.commit_group;");      // group: view v
        }
    }

    // ---- while loads fly: zero pads, build weight table ----
    if (tid < PADF) {
        sG[CHUNK + tid] = 0.f;
        sP[0][CHUNK + tid] = 0.f;
        sP[1][CHUNK + tid] = 0.f;
        sP[2][CHUNK + tid] = 0.f;
        sP[3][CHUNK + tid] = 0.f;
    }
    if (tid < 6) {
        float d = (float)tid;
        sg6[tid] = expf(-d * d * (1.0f / 4.5f));   // sigma = 1.5
    }
    __syncthreads();
    {
        float S = sg6[0] + 2.0f * (sg6[1] + sg6[2] + sg6[3] + sg6[4] + sg6[5]);
        float invS2 = 1.0f / (S * S);
        if (tid < 121) {
            int py = tid / 11, px = tid % 11;
            int dy = py - 5; if (dy < 0) dy = -dy;
            int dx = px - 5; if (dx < 0) dx = -dx;
            sW[tid] = sg6[dy] * sg6[dx] * invS2;
        } else if (tid < 128) {
            sW[tid] = 0.f;                          // tail patches contribute 0
        }
    }

    const int wid  = tid >> 5;
    const int lane = tid & 31;
    const int wbase = wid * ROW;

    // Accumulators: channels (0,1) packed, channel 2 scalar.
    ull  m1p[4], q2p[4], pgp[4];
    float m1s[4], q2s[4], pgs[4];
    ull  m2p = 0, g2p = 0;
    float m2s = 0.f, g2s = 0.f;
    #pragma unroll
    for (int v = 0; v < 4; v++) {
        m1p[v] = 0; q2p[v] = 0; pgp[v] = 0;
        m1s[v] = 0.f; q2s[v] = 0.f; pgs[v] = 0.f;
    }

    float wk[4];
    ull   bcp[4];    // cached gt (ch0,ch1) per k
    float bcs[4];    // cached gt ch2 per k

    // ---- gt phase: wait only the gt group (views still in flight) ----
    asm volatile("cp.async.wait_group 4;");
    __syncthreads();          // publishes gt buffer, pads, sW
    #pragma unroll
    for (int k = 0; k < 4; k++) wk[k] = sW[k * 32 + lane];

    #pragma unroll
    for (int k = 0; k < 4; k++) {
        const int base = wbase + 3 * (k * 32 + lane);
        const float w  = wk[k];
        const float b0 = sG[base + 0];
        const float b1 = sG[base + 1];
        const float b2 = sG[base + 2];
        const ull bp = pk2(b0, b1);
        const ull wp = pk2(w, w);
        bcp[k] = bp;  bcs[k] = b2;
        const ull wbp = mul2_(wp, bp);
        m2p = add2_(m2p, wbp);
        g2p = fma2_(wbp, bp, g2p);
        const float wb2 = w * b2;
        m2s += wb2;
        g2s = fmaf(wb2, b2, g2s);
    }

    // ---- view phase: wait everything, then k-outer / v-inner ----
    asm volatile("cp.async.wait_group 0;");
    __syncthreads();

    #pragma unroll
    for (int k = 0; k < 4; k++) {
        const int base = wbase + 3 * (k * 32 + lane);
        const float w  = wk[k];
        const ull  wp  = pk2(w, w);
        const ull  bp  = bcp[k];
        const float b2 = bcs[k];
        #pragma unroll
        for (int v = 0; v < 4; v++) {
            const float a0 = sP[v][base + 0];
            const float a1 = sP[v][base + 1];
            const float a2 = sP[v][base + 2];
            const ull ap = pk2(a0, a1);
            const ull wa = mul2_(wp, ap);
            m1p[v] = add2_(m1p[v], wa);
            q2p[v] = fma2_(wa, ap, q2p[v]);
            pgp[v] = fma2_(wa, bp, pgp[v]);
            const float wa2 = w * a2;
            m1s[v] += wa2;
            q2s[v] = fmaf(wa2, a2, q2s[v]);
            pgs[v] = fmaf(wa2, b2, pgs[v]);
        }
    }

    // Unpack to per-channel floats.
    float M1[4][3], Q2[4][3], PG[4][3], M2[3], G2[3];
    #pragma unroll
    for (int v = 0; v < 4; v++) {
        up2(m1p[v], M1[v][0], M1[v][1]);  M1[v][2] = m1s[v];
        up2(q2p[v], Q2[v][0], Q2[v][1]);  Q2[v][2] = q2s[v];
        up2(pgp[v], PG[v][0], PG[v][1]);  PG[v][2] = pgs[v];
    }
    up2(m2p, M2[0], M2[1]);  M2[2] = m2s;
    up2(g2p, G2[0], G2[1]);  G2[2] = g2s;

    // Fold across lane-bit-16: lanes 0-15 -> views 0,1; 16-31 -> views 2,3.
    const bool hi = (lane & 16) != 0;
    float val[24];
    #pragma unroll
    for (int c = 0; c < 3; c++) {
        float kA, kB;
        #define FOLD(slotA, slotB, idx) \
            kA = (slotA); kB = (slotB); \
            { float keep = hi ? kB : kA; float send = hi ? kA : kB; \
              val[idx] = keep + __shfl_xor_sync(0xFFFFFFFFu, send, 16); }
        FOLD(M1[0][c], M1[2][c], 0 + c);
        FOLD(Q2[0][c], Q2[2][c], 3 + c);
        FOLD(PG[0][c], PG[2][c], 6 + c);
        FOLD(M1[1][c], M1[3][c], 9 + c);
        FOLD(Q2[1][c], Q2[3][c], 12 + c);
        FOLD(PG[1][c], PG[3][c], 15 + c);
        FOLD(M2[c],    M2[c],    18 + c);   // single copy -> both halves get total
        FOLD(G2[c],    G2[c],    21 + c);
        #undef FOLD
    }

    // Butterfly within each 16-lane half.
    #pragma unroll
    for (int off = 8; off; off >>= 1) {
        #pragma unroll
        for (int i = 0; i < 24; i++)
            val[i] += __shfl_xor_sync(0xFFFFFFFFu, val[i], off);
    }

    // Epilogue: each lane computes SSIM for its half's two views.
    const float C1 = 1e-4f;   // 0.01^2
    const float C2 = 9e-4f;   // 0.03^2
    float ssim_lo = 0.f, ssim_hi_v = 0.f;
    #pragma unroll
    for (int c = 0; c < 3; c++) {
        float mu2  = val[18 + c];
        float mu2sq = mu2 * mu2;
        float s2   = val[21 + c] - mu2sq;
        {   // view lo
            float mu1 = val[0 + c];
            float mu1sq = mu1 * mu1;
            float mu12  = mu1 * mu2;
            float s1  = val[3 + c] - mu1sq;
            float s12 = val[6 + c] - mu12;
            float num = (2.0f * mu12 + C1) * (2.0f * s12 + C2);
            float den = (mu1sq + mu2sq + C1) * (s1 + s2 + C2);
            ssim_lo += __fdividef(num, den);
        }
        {   // view hi
            float mu1 = val[9 + c];
            float mu1sq = mu1 * mu1;
            float mu12  = mu1 * mu2;
            float s1  = val[12 + c] - mu1sq;
            float s12 = val[15 + c] - mu12;
            float num = (2.0f * mu12 + C1) * (2.0f * s12 + C2);
            float den = (mu1sq + mu2sq + C1) * (s1 + s2 + C2);
            ssim_hi_v += __fdividef(num, den);
        }
    }

    // Writers: lanes 0,1 (views 0,1) and 16,17 (views 2,3).
    if ((lane & 14) == 0) {
        const int q = q0 + wid;
        const int n = q >> 4;
        const int p = q & 15;
        int sel  = lane & 1;
        int view = ((lane >> 4) << 1) | sel;
        float res = (sel ? ssim_hi_v : ssim_lo) * (1.0f / 3.0f);
        out[(view * NN + n) * NP + p] = res;
    }
}

extern "C" void kernel_launch(void* const* d_in, const int* in_sizes, int n_in,
                              void* d_out, int out_size)
{
    const float* pred = (const float*)d_in[0];   // img_pred [4,2048,16,121,3]
    const float* gt   = (const float*)d_in[1];   // img_gt   [2048,16,121,3]
    float* out = (float*)d_out;                  // [4,2048,16]

    const int blocks = (NN * NP) / RPB;          // 8192 blocks, 4 rows each
    ssim_kernel<<<blocks, 128>>>(pred, gt, out);
}